// round 1
// baseline (speedup 1.0000x reference)
#include <cuda_runtime.h>
#include <cstdint>
#include <cmath>

// ---------------------------------------------------------------------------
// SpatialPatchMoE: x[2,64,8,128,128] fp32, P=8 patches -> N=512, L=8, E=8, K=2
//
// Decomposition: depthwise conv is (1,7,7) and LN/pointwise are per-position,
// so everything after the router splits across (patch, l) slices of shape
// [C=64, 64 positions]. out = x + sum_{top2} w_e * h_e(x)   (softmax weights
// sum to 1, so residual factors out).
// ---------------------------------------------------------------------------

#define NPATCH 512
#define HP 66                     // smem pitch for hd/glu (even -> float2 ok)

__device__ int   g_topi[NPATCH][2];
__device__ float g_topw[NPATCH][2];

// ---------------------------------------------------------------------------
// Router: per-patch mean over (L,P,P) per channel -> logits -> top2 softmax
// ---------------------------------------------------------------------------
__global__ __launch_bounds__(256) void router_kernel(
    const float* __restrict__ x,
    const float* __restrict__ rw,
    const float* __restrict__ rb)
{
    int n  = blockIdx.x;
    int b  = n >> 8;
    int ph = (n >> 4) & 15;
    int pw = n & 15;
    int t    = threadIdx.x;
    int lane = t & 31;
    int warp = t >> 5;
    int i4 = lane >> 3;           // 0..3  (covers rows i4 and i4+4)
    int j  = lane & 7;

    __shared__ float sm[64];
    __shared__ float logits[8];

    // each warp owns 8 channels; lanes cover (i,j) for good sector reuse
    for (int r = 0; r < 8; ++r) {
        int c = warp * 8 + r;
        const float* xc = x + ((long)b*64 + c)*131072 + (ph*8)*128 + pw*8;
        float s = 0.f;
        #pragma unroll
        for (int l = 0; l < 8; ++l) {
            long base = (long)l * 16384;
            s += xc[base + i4*128 + j];
            s += xc[base + (i4+4)*128 + j];
        }
        #pragma unroll
        for (int off = 16; off; off >>= 1) s += __shfl_xor_sync(0xFFFFFFFFu, s, off);
        if (lane == 0) sm[c] = s * (1.f/512.f);
    }
    __syncthreads();

    if (t < 8) {
        float acc = rb[t];
        const float* w = rw + t*64;
        #pragma unroll
        for (int c = 0; c < 64; ++c) acc += sm[c] * w[c];
        logits[t] = acc;
    }
    __syncthreads();

    if (t == 0) {
        int i0 = 0; float v0 = logits[0];
        #pragma unroll
        for (int e = 1; e < 8; ++e) if (logits[e] > v0) { v0 = logits[e]; i0 = e; }
        int i1 = -1; float v1 = -3.4e38f;
        #pragma unroll
        for (int e = 0; e < 8; ++e) if (e != i0 && logits[e] > v1) { v1 = logits[e]; i1 = e; }
        float e1  = __expf(v1 - v0);        // v0 is max
        float inv = 1.f / (1.f + e1);
        g_topi[n][0] = i0; g_topi[n][1] = i1;
        g_topw[n][0] = inv; g_topw[n][1] = e1 * inv;
    }
}

// ---------------------------------------------------------------------------
// Main: one block per (patch, l) slice. 256 threads = 8 warps.
//   warp w owns output channels w*8..w*8+7; lane owns position pair (2*lane,
//   2*lane+1) -> float2 everywhere in the GEMM phases.
// smem: xs[64*64] input slice, hd[64*HP] dwconv+LN, glu[64*HP]
// ---------------------------------------------------------------------------
extern __shared__ float smem_dyn[];

__global__ __launch_bounds__(256) void moe_kernel(
    const float* __restrict__ x,
    const float* __restrict__ dw_w,  const float* __restrict__ dw_b,
    const float* __restrict__ ln_w,  const float* __restrict__ ln_b,
    const float* __restrict__ pwi_w, const float* __restrict__ pwi_b,
    const float* __restrict__ pwo_w, const float* __restrict__ pwo_b,
    float* __restrict__ out)
{
    float* xs  = smem_dyn;            // 4096 floats
    float* hd  = smem_dyn + 4096;     // 64*HP
    float* glu = hd + 64*HP;          // 64*HP

    int s = blockIdx.x;
    int n = s >> 3, l = s & 7;
    int b = n >> 8, ph = (n >> 4) & 15, pw = n & 15;
    int t    = threadIdx.x;
    int lane = t & 31;
    int warp = t >> 5;

    // x[b,c,l,ph*8+i,pw*8+j] = x[gbase + c*131072 + i*128 + j]
    const long gbase = (long)b*64*131072 + (long)l*16384 + (ph*8)*128 + pw*8;

    // ---- load slice into smem ----
    for (int idx = t; idx < 4096; idx += 256) {
        int c = idx >> 6, p = idx & 63;
        xs[idx] = x[gbase + (long)c*131072 + (p >> 3)*128 + (p & 7)];
    }

    int   e0 = g_topi[n][0], e1 = g_topi[n][1];
    float w0 = g_topw[n][0], w1 = g_topw[n][1];

    float2 osum[8];
    #pragma unroll
    for (int r = 0; r < 8; ++r) osum[r] = make_float2(0.f, 0.f);

    __syncthreads();

    const int p0 = lane * 2;              // even -> (p0, p0+1) share the row
    const int ir = p0 >> 3;               // row 0..7
    const int j0 = p0 & 7;                // col (even)

    for (int k = 0; k < 2; ++k) {
        const int   e  = k ? e1 : e0;
        const float we = k ? w1 : w0;

        // ---- depthwise 7x7 conv, SAME padding on the 8x8 patch ----
        {
            const float* dwb = dw_b + e*64;
            for (int r = 0; r < 8; ++r) {
                int c = warp*8 + r;
                const float* W  = dw_w + ((long)e*64 + c)*49;
                const float* xc = xs + c*64;
                float a0 = __ldg(&dwb[c]);
                float a1 = a0;
                #pragma unroll
                for (int di = -3; di <= 3; ++di) {
                    int ii = ir + di;
                    if ((unsigned)ii < 8u) {
                        const float* xrow = xc + ii*8;
                        const float* Wr   = W + (di+3)*7;
                        #pragma unroll
                        for (int dj = -3; dj <= 3; ++dj) {
                            float wv = __ldg(&Wr[dj+3]);
                            int jj0 = j0 + dj;
                            int jj1 = jj0 + 1;
                            if ((unsigned)jj0 < 8u) a0 += wv * xrow[jj0];
                            if ((unsigned)jj1 < 8u) a1 += wv * xrow[jj1];
                        }
                    }
                }
                hd[c*HP + p0]     = a0;
                hd[c*HP + p0 + 1] = a1;
            }
        }
        __syncthreads();

        // ---- LayerNorm over the 64 positions of each channel ----
        if (t < 64) {
            float* hc = hd + t*HP;
            float sum = 0.f, sq = 0.f;
            #pragma unroll
            for (int p = 0; p < 64; ++p) { float v = hc[p]; sum += v; sq += v*v; }
            float mu   = sum * (1.f/64.f);
            float var  = sq  * (1.f/64.f) - mu*mu;
            float rstd = rsqrtf(var + 1e-5f);
            const float* lw = ln_w + e*64;
            const float* lb = ln_b + e*64;
            #pragma unroll
            for (int p = 0; p < 64; ++p)
                hc[p] = (hc[p] - mu) * rstd * __ldg(&lw[p]) + __ldg(&lb[p]);
        }
        __syncthreads();

        // ---- pw_in (C -> 2C) + GLU ----
        {
            const float* bi = pwi_b + e*128;
            for (int r = 0; r < 8; ++r) {
                int o = warp*8 + r;
                const float* Wa = pwi_w + ((long)e*128 + o)*64;
                const float* Wg = Wa + 64*64;
                float ba = __ldg(&bi[o]), bg = __ldg(&bi[o+64]);
                float2 a = make_float2(ba, ba);
                float2 g = make_float2(bg, bg);
                #pragma unroll
                for (int c = 0; c < 64; ++c) {
                    float2 h  = *(const float2*)(hd + c*HP + p0);
                    float  wa = __ldg(&Wa[c]);
                    float  wg = __ldg(&Wg[c]);
                    a.x += wa*h.x; a.y += wa*h.y;
                    g.x += wg*h.x; g.y += wg*h.y;
                }
                float s0 = a.x / (1.f + __expf(-a.x));   // silu
                float s1 = a.y / (1.f + __expf(-a.y));
                glu[o*HP + p0]     = s0 * g.x;
                glu[o*HP + p0 + 1] = s1 * g.y;
            }
        }
        __syncthreads();

        // ---- pw_out (C -> C), weighted accumulate in registers ----
        {
            const float* bo = pwo_b + e*64;
            for (int r = 0; r < 8; ++r) {
                int o = warp*8 + r;
                const float* Wo = pwo_w + ((long)e*64 + o)*64;
                float bb = __ldg(&bo[o]);
                float2 a = make_float2(bb, bb);
                #pragma unroll
                for (int c = 0; c < 64; ++c) {
                    float2 h  = *(const float2*)(glu + c*HP + p0);
                    float  wv = __ldg(&Wo[c]);
                    a.x += wv*h.x; a.y += wv*h.y;
                }
                osum[r].x += we * a.x;
                osum[r].y += we * a.y;
            }
        }
        __syncthreads();
    }

    // ---- out = x + sum_k w_k * h_k ----
    #pragma unroll
    for (int r = 0; r < 8; ++r) {
        int o = warp*8 + r;
        float2 v;
        v.x = xs[o*64 + p0]     + osum[r].x;
        v.y = xs[o*64 + p0 + 1] + osum[r].y;
        *(float2*)(out + gbase + (long)o*131072 + ir*128 + j0) = v;
    }
}

// ---------------------------------------------------------------------------
extern "C" void kernel_launch(void* const* d_in, const int* in_sizes, int n_in,
                              void* d_out, int out_size)
{
    const float* x        = (const float*)d_in[0];
    const float* router_w = (const float*)d_in[1];
    const float* router_b = (const float*)d_in[2];
    const float* dw_w     = (const float*)d_in[3];
    const float* dw_b     = (const float*)d_in[4];
    const float* ln_w     = (const float*)d_in[5];
    const float* ln_b     = (const float*)d_in[6];
    const float* pwi_w    = (const float*)d_in[7];
    const float* pwi_b    = (const float*)d_in[8];
    const float* pwo_w    = (const float*)d_in[9];
    const float* pwo_b    = (const float*)d_in[10];
    float* out = (float*)d_out;

    router_kernel<<<NPATCH, 256>>>(x, router_w, router_b);

    const int smem_bytes = (4096 + 2*64*HP) * sizeof(float);   // 50176
    cudaFuncSetAttribute(moe_kernel,
                         cudaFuncAttributeMaxDynamicSharedMemorySize, smem_bytes);
    moe_kernel<<<4096, 256, smem_bytes>>>(x, dw_w, dw_b, ln_w, ln_b,
                                          pwi_w, pwi_b, pwo_w, pwo_b, out);
}

// round 3
// speedup vs baseline: 2.0688x; 2.0688x over previous
#include <cuda_runtime.h>
#include <cstdint>
#include <cmath>

// ---------------------------------------------------------------------------
// SpatialPatchMoE: x[2,64,8,128,128] fp32, P=8 -> N=512 patches, L=8, E=8, K=2
// out = x + sum_{top2} w_e * GatedConvBlock_e(x)   (residual factored out since
// softmax weights sum to 1). Work unit: (patch, l) slice = [C=64][64 positions].
//
// Round 3 = round 2 re-bench (infra failure last round): register-blocked
// GEMMs (4x4 lane tiles, a/g fused) with weights transposed into smem;
// dwconv with zero-padded rows + 14-wide windows; parallel LN.
// ---------------------------------------------------------------------------

#define NPATCH 512

// smem layout (floats)
#define XS_CP   116               // per-channel pitch (8 rows x 14 + pad)
#define XS_SZ   (64*XS_CP)        // 7424
#define HD_OFF  7424
#define HD_P    68
#define WT1_OFF (HD_OFF + 64*HD_P)     // 11776
#define WT1_P   132
#define WT2_OFF (WT1_OFF + 64*WT1_P)   // 20224
#define WT2_P   68
#define SMEM_FLOATS (WT2_OFF + 64*WT2_P)   // 24576 -> 98304 bytes

__device__ int   g_topi[NPATCH][2];
__device__ float g_topw[NPATCH][2];

// ---------------------------------------------------------------------------
// Router: per-patch channel means -> 8 logits -> top2 softmax
// ---------------------------------------------------------------------------
__global__ __launch_bounds__(256) void router_kernel(
    const float* __restrict__ x,
    const float* __restrict__ rw,
    const float* __restrict__ rb)
{
    int n  = blockIdx.x;
    int b  = n >> 8;
    int ph = (n >> 4) & 15;
    int pw = n & 15;
    int t    = threadIdx.x;
    int lane = t & 31;
    int warp = t >> 5;
    int i4 = lane >> 3;
    int j  = lane & 7;

    __shared__ float sm[64];
    __shared__ float logits[8];

    for (int r = 0; r < 8; ++r) {
        int c = warp * 8 + r;
        const float* xc = x + ((long)b*64 + c)*131072 + (ph*8)*128 + pw*8;
        float s = 0.f;
        #pragma unroll
        for (int l = 0; l < 8; ++l) {
            long base = (long)l * 16384;
            s += xc[base + i4*128 + j];
            s += xc[base + (i4+4)*128 + j];
        }
        #pragma unroll
        for (int off = 16; off; off >>= 1) s += __shfl_xor_sync(0xFFFFFFFFu, s, off);
        if (lane == 0) sm[c] = s * (1.f/512.f);
    }
    __syncthreads();

    if (t < 8) {
        float acc = rb[t];
        const float* w = rw + t*64;
        #pragma unroll
        for (int c = 0; c < 64; ++c) acc += sm[c] * w[c];
        logits[t] = acc;
    }
    __syncthreads();

    if (t == 0) {
        int i0 = 0; float v0 = logits[0];
        #pragma unroll
        for (int e = 1; e < 8; ++e) if (logits[e] > v0) { v0 = logits[e]; i0 = e; }
        int i1 = -1; float v1 = -3.4e38f;
        #pragma unroll
        for (int e = 0; e < 8; ++e) if (e != i0 && logits[e] > v1) { v1 = logits[e]; i1 = e; }
        float e1  = __expf(v1 - v0);
        float inv = 1.f / (1.f + e1);
        g_topi[n][0] = i0; g_topi[n][1] = i1;
        g_topw[n][0] = inv; g_topw[n][1] = e1 * inv;
    }
}

// ---------------------------------------------------------------------------
// Main kernel: one block per (patch, l) slice; 256 threads = 8 warps.
// ---------------------------------------------------------------------------
extern __shared__ float smem_dyn[];

__global__ __launch_bounds__(256, 2) void moe_kernel(
    const float* __restrict__ x,
    const float* __restrict__ dw_w,  const float* __restrict__ dw_b,
    const float* __restrict__ ln_w,  const float* __restrict__ ln_b,
    const float* __restrict__ pwi_w, const float* __restrict__ pwi_b,
    const float* __restrict__ pwo_w, const float* __restrict__ pwo_b,
    float* __restrict__ out)
{
    float* xs  = smem_dyn;              // padded input slice
    float* hd  = smem_dyn + HD_OFF;     // dwconv/LN output, later GLU output
    float* wt1 = smem_dyn + WT1_OFF;    // pw_in weights transposed [k][128]
    float* wt2 = smem_dyn + WT2_OFF;    // pw_out weights transposed [k][64]

    int s = blockIdx.x;
    int n = s >> 3, l = s & 7;
    int b = n >> 8, ph = (n >> 4) & 15, pwi_ = n & 15;
    int t    = threadIdx.x;
    int lane = t & 31;
    int warp = t >> 5;

    const long gbase = (long)b*64*131072 + (long)l*16384 + (ph*8)*128 + pwi_*8;

    // ---- zero only the pad lanes of each padded row, fill interior ----
    // rows: [0..2]=left pad zeros, [3..10]=data, [11..13]=right pad zeros
    {
        // 64 ch * 8 rows = 512 rows; each thread pads 2 rows (6 stores)
        for (int rid = t; rid < 512; rid += 256) {
            float* row = xs + (rid >> 3)*XS_CP + (rid & 7)*14;
            row[0] = 0.f; row[1] = 0.f; row[2] = 0.f;
            row[11] = 0.f; row[12] = 0.f; row[13] = 0.f;
        }
    }
    for (int idx = t; idx < 4096; idx += 256) {
        int c = idx >> 6, p = idx & 63, i = p >> 3, j = p & 7;
        xs[c*XS_CP + i*14 + 3 + j] = x[gbase + (long)c*131072 + i*128 + j];
    }

    int   e0 = g_topi[n][0], e1i = g_topi[n][1];
    float wgt0 = g_topw[n][0], wgt1 = g_topw[n][1];

    // lane tiling shared by GEMM1/GEMM2/output
    const int lo = lane >> 3;               // 0..3
    const int lp = lane & 7;                // 0..7
    const int ot = warp >> 1;               // 0..3
    const int pt = warp & 1;                // 0..1
    const int pb = pt*32 + lp*4;            // 4 consecutive positions
    const int ob = ot*16 + lo*4;            // 4 consecutive outputs / o-pairs

    float osum[4][4];
    #pragma unroll
    for (int r = 0; r < 4; ++r)
        #pragma unroll
        for (int q = 0; q < 4; ++q) osum[r][q] = 0.f;

    // dwconv per-thread assignment
    const int dc_c  = t >> 2;               // channel 0..63
    const int dc_rr = (t & 3) * 2;          // output rows rr, rr+1

    __syncthreads();

    for (int kk = 0; kk < 2; ++kk) {
        const int   e  = kk ? e1i : e0;
        const float we = kk ? wgt1 : wgt0;

        // ================= Phase A: dwconv + weight transposes ==============
        {   // depthwise 7x7 conv: thread computes 2 full output rows (8 wide)
            const float* W = dw_w + ((long)e*64 + dc_c)*49;
            float bias = __ldg(&dw_b[e*64 + dc_c]);
            float a0[8], a1[8];
            #pragma unroll
            for (int j = 0; j < 8; ++j) { a0[j] = bias; a1[j] = bias; }

            int ii_lo = dc_rr - 3; if (ii_lo < 0) ii_lo = 0;
            int ii_hi = dc_rr + 4; if (ii_hi > 7) ii_hi = 7;
            for (int ii = ii_lo; ii <= ii_hi; ++ii) {
                const float* xr = xs + dc_c*XS_CP + ii*14;
                float win[14];
                #pragma unroll
                for (int u = 0; u < 14; ++u) win[u] = xr[u];
                int di0 = ii - dc_rr + 3;           // tap row for out row rr
                if (di0 <= 6) {
                    const float* Wr = W + di0*7;
                    #pragma unroll
                    for (int dj = 0; dj < 7; ++dj) {
                        float wv = __ldg(&Wr[dj]);
                        #pragma unroll
                        for (int j = 0; j < 8; ++j) a0[j] += wv * win[dj + j];
                    }
                }
                if (di0 >= 1) {                     // tap row di0-1 for rr+1
                    const float* Wr = W + (di0-1)*7;
                    #pragma unroll
                    for (int dj = 0; dj < 7; ++dj) {
                        float wv = __ldg(&Wr[dj]);
                        #pragma unroll
                        for (int j = 0; j < 8; ++j) a1[j] += wv * win[dj + j];
                    }
                }
            }
            float* h0 = hd + dc_c*HD_P + dc_rr*8;
            *(float4*)(h0)      = make_float4(a0[0], a0[1], a0[2], a0[3]);
            *(float4*)(h0 + 4)  = make_float4(a0[4], a0[5], a0[6], a0[7]);
            *(float4*)(h0 + 8)  = make_float4(a1[0], a1[1], a1[2], a1[3]);
            *(float4*)(h0 + 12) = make_float4(a1[4], a1[5], a1[6], a1[7]);
        }
        {   // pw_in weight transpose: [128][64] -> wt1[k][o'] (o'=0..127)
            const float* src = pwi_w + (long)e*8192;
            int o = t >> 1, cb = (t & 1) * 32;
            #pragma unroll
            for (int u = 0; u < 8; ++u) {
                float4 v = *(const float4*)(src + o*64 + cb + u*4);
                int c = cb + u*4;
                wt1[(c+0)*WT1_P + o] = v.x;
                wt1[(c+1)*WT1_P + o] = v.y;
                wt1[(c+2)*WT1_P + o] = v.z;
                wt1[(c+3)*WT1_P + o] = v.w;
            }
        }
        {   // pw_out weight transpose: [64][64] -> wt2[k][o]
            const float* src = pwo_w + (long)e*4096;
            int o = t >> 2, cb = (t & 3) * 16;
            #pragma unroll
            for (int u = 0; u < 4; ++u) {
                float4 v = *(const float4*)(src + o*64 + cb + u*4);
                int c = cb + u*4;
                wt2[(c+0)*WT2_P + o] = v.x;
                wt2[(c+1)*WT2_P + o] = v.y;
                wt2[(c+2)*WT2_P + o] = v.z;
                wt2[(c+3)*WT2_P + o] = v.w;
            }
        }
        __syncthreads();

        // ================= Phase B: LayerNorm over 64 positions =============
        {
            int c   = warp*8 + (lane >> 2);
            int sub = lane & 3;
            float* hc = hd + c*HD_P + sub*16;
            float v[16];
            #pragma unroll
            for (int u = 0; u < 4; ++u) {
                float4 f = *(const float4*)(hc + u*4);
                v[u*4+0]=f.x; v[u*4+1]=f.y; v[u*4+2]=f.z; v[u*4+3]=f.w;
            }
            float sum = 0.f, sq = 0.f;
            #pragma unroll
            for (int u = 0; u < 16; ++u) { sum += v[u]; sq += v[u]*v[u]; }
            sum += __shfl_xor_sync(0xFFFFFFFFu, sum, 1);
            sq  += __shfl_xor_sync(0xFFFFFFFFu, sq, 1);
            sum += __shfl_xor_sync(0xFFFFFFFFu, sum, 2);
            sq  += __shfl_xor_sync(0xFFFFFFFFu, sq, 2);
            float mu   = sum * (1.f/64.f);
            float var  = sq  * (1.f/64.f) - mu*mu;
            float rstd = rsqrtf(var + 1e-5f);
            const float* lw = ln_w + e*64 + sub*16;
            const float* lb = ln_b + e*64 + sub*16;
            #pragma unroll
            for (int u = 0; u < 16; ++u)
                v[u] = (v[u] - mu) * rstd * __ldg(&lw[u]) + __ldg(&lb[u]);
            #pragma unroll
            for (int u = 0; u < 4; ++u)
                *(float4*)(hc + u*4) = make_float4(v[u*4+0],v[u*4+1],v[u*4+2],v[u*4+3]);
        }
        __syncthreads();

        // ============== Phase C1: GEMM1 (pw_in, a & g halves) ===============
        // lane: o-pairs ob..ob+3 (a at o, g at o+64), positions pb..pb+3
        float aA[4][4], aG[4][4];
        #pragma unroll
        for (int r = 0; r < 4; ++r)
            #pragma unroll
            for (int q = 0; q < 4; ++q) { aA[r][q] = 0.f; aG[r][q] = 0.f; }

        #pragma unroll 4
        for (int k = 0; k < 64; ++k) {
            float wa[4], wg[4], h[4];
            *(float4*)wa = *(const float4*)(wt1 + k*WT1_P + ob);
            *(float4*)wg = *(const float4*)(wt1 + k*WT1_P + 64 + ob);
            *(float4*)h  = *(const float4*)(hd  + k*HD_P  + pb);
            #pragma unroll
            for (int r = 0; r < 4; ++r)
                #pragma unroll
                for (int q = 0; q < 4; ++q) {
                    aA[r][q] += wa[r] * h[q];
                    aG[r][q] += wg[r] * h[q];
                }
        }
        __syncthreads();   // all reads of hd done before GLU overwrites it

        // ============== Phase C2: GLU -> hd (reused as glu buffer) ==========
        {
            const float* bi = pwi_b + e*128;
            #pragma unroll
            for (int r = 0; r < 4; ++r) {
                float ba = __ldg(&bi[ob + r]);
                float bg = __ldg(&bi[64 + ob + r]);
                float res[4];
                #pragma unroll
                for (int q = 0; q < 4; ++q) {
                    float a = aA[r][q] + ba;
                    float g = aG[r][q] + bg;
                    float sig = 1.f / (1.f + __expf(-a));
                    res[q] = a * sig * g;
                }
                *(float4*)(hd + (ob + r)*HD_P + pb) =
                    make_float4(res[0], res[1], res[2], res[3]);
            }
        }
        __syncthreads();

        // ============== Phase D: GEMM2 (pw_out) -> osum =====================
        {
            float acc[4][4];
            #pragma unroll
            for (int r = 0; r < 4; ++r)
                #pragma unroll
                for (int q = 0; q < 4; ++q) acc[r][q] = 0.f;

            #pragma unroll 4
            for (int k = 0; k < 64; ++k) {
                float w[4], h[4];
                *(float4*)w = *(const float4*)(wt2 + k*WT2_P + ob);
                *(float4*)h = *(const float4*)(hd  + k*HD_P  + pb);
                #pragma unroll
                for (int r = 0; r < 4; ++r)
                    #pragma unroll
                    for (int q = 0; q < 4; ++q) acc[r][q] += w[r] * h[q];
            }
            const float* bo = pwo_b + e*64;
            #pragma unroll
            for (int r = 0; r < 4; ++r) {
                float bb = __ldg(&bo[ob + r]);
                #pragma unroll
                for (int q = 0; q < 4; ++q)
                    osum[r][q] += we * (acc[r][q] + bb);
            }
        }
        __syncthreads();   // hd/wt free for next expert
    }

    // ---- out = x + sum_k w_k * h_k ----
    {
        const int ir = pb >> 3;
        const int j0 = pb & 7;
        #pragma unroll
        for (int r = 0; r < 4; ++r) {
            int o = ob + r;
            const float* xr = xs + o*XS_CP + ir*14 + 3 + j0;
            float4 v;
            v.x = xr[0] + osum[r][0];
            v.y = xr[1] + osum[r][1];
            v.z = xr[2] + osum[r][2];
            v.w = xr[3] + osum[r][3];
            *(float4*)(out + gbase + (long)o*131072 + ir*128 + j0) = v;
        }
    }
}

// ---------------------------------------------------------------------------
extern "C" void kernel_launch(void* const* d_in, const int* in_sizes, int n_in,
                              void* d_out, int out_size)
{
    const float* x        = (const float*)d_in[0];
    const float* router_w = (const float*)d_in[1];
    const float* router_b = (const float*)d_in[2];
    const float* dw_w     = (const float*)d_in[3];
    const float* dw_b     = (const float*)d_in[4];
    const float* ln_w     = (const float*)d_in[5];
    const float* ln_b     = (const float*)d_in[6];
    const float* pwi_w    = (const float*)d_in[7];
    const float* pwi_b    = (const float*)d_in[8];
    const float* pwo_w    = (const float*)d_in[9];
    const float* pwo_b    = (const float*)d_in[10];
    float* out = (float*)d_out;

    router_kernel<<<NPATCH, 256>>>(x, router_w, router_b);

    const int smem_bytes = SMEM_FLOATS * sizeof(float);   // 98304
    cudaFuncSetAttribute(moe_kernel,
                         cudaFuncAttributeMaxDynamicSharedMemorySize, smem_bytes);
    moe_kernel<<<4096, 256, smem_bytes>>>(x, dw_w, dw_b, ln_w, ln_b,
                                          pwi_w, pwi_b, pwo_w, pwo_b, out);
}

// round 4
// speedup vs baseline: 2.3822x; 1.1515x over previous
#include <cuda_runtime.h>
#include <cstdint>
#include <cmath>

// ---------------------------------------------------------------------------
// SpatialPatchMoE: x[2,64,8,128,128] fp32, P=8 -> N=512 patches, L=8, E=8, K=2
// out = x + sum_{top2} w_e * GatedConvBlock_e(x)
// Round 4: pre-transposed weights (device globals), packed fma.rn.f32x2 in
// GEMMs + dwconv, vectorized dwconv windows (row pitch 16).
// ---------------------------------------------------------------------------

#define NPATCH 512

// smem layout (floats)
#define XS_CP   132               // per-channel pitch: 8 rows x 16 + 4
#define HD_OFF  8448              // 64*132
#define HD_P    68
#define WT1_OFF (HD_OFF + 64*HD_P)      // 12800
#define WT2_OFF (WT1_OFF + 64*128)      // 20992
#define SMEM_FLOATS (WT2_OFF + 64*64)   // 25088 -> 100352 bytes

typedef unsigned long long ull;

__device__ __forceinline__ ull pk2(float lo, float hi) {
    ull r; asm("mov.b64 %0, {%1, %2};" : "=l"(r) : "f"(lo), "f"(hi)); return r;
}
__device__ __forceinline__ ull dup2(float v) {
    ull r; asm("mov.b64 %0, {%1, %1};" : "=l"(r) : "f"(v)); return r;
}
__device__ __forceinline__ void fma2(ull& d, ull a, ull b) {
    asm("fma.rn.f32x2 %0, %1, %2, %0;" : "+l"(d) : "l"(a), "l"(b));
}
__device__ __forceinline__ float2 up2(ull v) {
    float2 f; asm("mov.b64 {%0, %1}, %2;" : "=f"(f.x), "=f"(f.y) : "l"(v)); return f;
}

__device__ int   g_topi[NPATCH][2];
__device__ float g_topw[NPATCH][2];
__device__ float g_wt1[8][64*128];   // pw_in^T  : [e][k][o'] o'=0..127
__device__ float g_wt2[8][64*64];    // pw_out^T : [e][k][o]

// ---------------------------------------------------------------------------
// One-time weight transpose (runs every launch; tiny)
// ---------------------------------------------------------------------------
__global__ __launch_bounds__(256) void transpose_kernel(
    const float* __restrict__ pwi_w, const float* __restrict__ pwo_w)
{
    int e = blockIdx.x, t = threadIdx.x;
    const float* s1 = pwi_w + (long)e*8192;
    float* d1 = g_wt1[e];
    for (int i = t; i < 8192; i += 256) {
        int o = i >> 6, k = i & 63;
        d1[(k << 7) | o] = s1[i];
    }
    const float* s2 = pwo_w + (long)e*4096;
    float* d2 = g_wt2[e];
    for (int i = t; i < 4096; i += 256) {
        int o = i >> 6, k = i & 63;
        d2[(k << 6) | o] = s2[i];
    }
}

// ---------------------------------------------------------------------------
// Router: per-patch channel means -> 8 logits -> top2 softmax
// ---------------------------------------------------------------------------
__global__ __launch_bounds__(256) void router_kernel(
    const float* __restrict__ x,
    const float* __restrict__ rw,
    const float* __restrict__ rb)
{
    int n  = blockIdx.x;
    int b  = n >> 8;
    int ph = (n >> 4) & 15;
    int pw = n & 15;
    int t    = threadIdx.x;
    int lane = t & 31;
    int warp = t >> 5;
    int i4 = lane >> 3;
    int j  = lane & 7;

    __shared__ float sm[64];
    __shared__ float logits[8];

    for (int r = 0; r < 8; ++r) {
        int c = warp * 8 + r;
        const float* xc = x + ((long)b*64 + c)*131072 + (ph*8)*128 + pw*8;
        float s = 0.f;
        #pragma unroll
        for (int l = 0; l < 8; ++l) {
            long base = (long)l * 16384;
            s += xc[base + i4*128 + j];
            s += xc[base + (i4+4)*128 + j];
        }
        #pragma unroll
        for (int off = 16; off; off >>= 1) s += __shfl_xor_sync(0xFFFFFFFFu, s, off);
        if (lane == 0) sm[c] = s * (1.f/512.f);
    }
    __syncthreads();

    if (t < 8) {
        float acc = rb[t];
        const float* w = rw + t*64;
        #pragma unroll
        for (int c = 0; c < 64; ++c) acc += sm[c] * w[c];
        logits[t] = acc;
    }
    __syncthreads();

    if (t == 0) {
        int i0 = 0; float v0 = logits[0];
        #pragma unroll
        for (int e = 1; e < 8; ++e) if (logits[e] > v0) { v0 = logits[e]; i0 = e; }
        int i1 = -1; float v1 = -3.4e38f;
        #pragma unroll
        for (int e = 0; e < 8; ++e) if (e != i0 && logits[e] > v1) { v1 = logits[e]; i1 = e; }
        float e1  = __expf(v1 - v0);
        float inv = 1.f / (1.f + e1);
        g_topi[n][0] = i0; g_topi[n][1] = i1;
        g_topw[n][0] = inv; g_topw[n][1] = e1 * inv;
    }
}

// ---------------------------------------------------------------------------
// Main kernel: one block per (patch, l) slice; 256 threads = 8 warps.
// ---------------------------------------------------------------------------
extern __shared__ float smem_dyn[];

__global__ __launch_bounds__(256, 2) void moe_kernel(
    const float* __restrict__ x,
    const float* __restrict__ dw_w,  const float* __restrict__ dw_b,
    const float* __restrict__ ln_w,  const float* __restrict__ ln_b,
    const float* __restrict__ pwi_b, const float* __restrict__ pwo_b,
    float* __restrict__ out)
{
    float* xs  = smem_dyn;              // padded input slice (pitch 132)
    float* hd  = smem_dyn + HD_OFF;     // dwconv/LN output, later GLU output
    float* wt1 = smem_dyn + WT1_OFF;    // pw_in^T  [k][128]
    float* wt2 = smem_dyn + WT2_OFF;    // pw_out^T [k][64]

    int s = blockIdx.x;
    int n = s >> 3, l = s & 7;
    int b = n >> 8, ph = (n >> 4) & 15, pwn = n & 15;
    int t    = threadIdx.x;
    int lane = t & 31;
    int warp = t >> 5;

    const long gbase = (long)b*64*131072 + (long)l*16384 + (ph*8)*128 + pwn*8;

    // ---- zero pad lanes {0,1,2,11,12,13} of each 16-float row; fill data ----
    for (int rid = t; rid < 512; rid += 256) {
        float* row = xs + (rid >> 3)*XS_CP + (rid & 7)*16;
        row[0] = 0.f; row[1] = 0.f; row[2] = 0.f;
        row[11] = 0.f; row[12] = 0.f; row[13] = 0.f;
    }
    for (int idx = t; idx < 4096; idx += 256) {
        int c = idx >> 6, p = idx & 63, i = p >> 3, j = p & 7;
        xs[c*XS_CP + i*16 + 3 + j] = x[gbase + (long)c*131072 + i*128 + j];
    }

    int   e0 = g_topi[n][0], e1i = g_topi[n][1];
    float wgt0 = g_topw[n][0], wgt1 = g_topw[n][1];

    // lane tiling shared by GEMM1/GEMM2/output
    const int lo = lane >> 3;               // 0..3
    const int lp = lane & 7;                // 0..7
    const int ot = warp >> 1;               // 0..3
    const int pt = warp & 1;                // 0..1
    const int pb = pt*32 + lp*4;            // 4 consecutive positions
    const int ob = ot*16 + lo*4;            // 4 consecutive outputs

    float osum[4][4];
    #pragma unroll
    for (int r = 0; r < 4; ++r)
        #pragma unroll
        for (int q = 0; q < 4; ++q) osum[r][q] = 0.f;

    // dwconv per-thread assignment
    const int dc_c  = t >> 2;               // channel 0..63
    const int dc_rr = (t & 3) * 2;          // output rows rr, rr+1

    __syncthreads();

    for (int kk = 0; kk < 2; ++kk) {
        const int   e  = kk ? e1i : e0;
        const float we = kk ? wgt1 : wgt0;

        // ============ Phase A: dwconv (f32x2 row pairs) + weight copies =====
        {
            const float* W = dw_w + ((long)e*64 + dc_c)*49;
            float bias = __ldg(&dw_b[e*64 + dc_c]);
            ull acc[8];
            #pragma unroll
            for (int j = 0; j < 8; ++j) acc[j] = dup2(bias);

            float wprev[7];
            #pragma unroll
            for (int u = 0; u < 7; ++u) wprev[u] = 0.f;

            #pragma unroll
            for (int di = 0; di < 8; ++di) {
                float wcur[7];
                #pragma unroll
                for (int u = 0; u < 7; ++u)
                    wcur[u] = (di <= 6) ? __ldg(&W[di*7 + u]) : 0.f;
                int ii = dc_rr + di - 3;
                if (ii >= 0 && ii <= 7) {
                    const float* xr = xs + dc_c*XS_CP + ii*16;
                    float4 v0 = *(const float4*)(xr);
                    float4 v1 = *(const float4*)(xr + 4);
                    float4 v2 = *(const float4*)(xr + 8);
                    float4 v3 = *(const float4*)(xr + 12);
                    float win[14] = {v0.x,v0.y,v0.z,v0.w, v1.x,v1.y,v1.z,v1.w,
                                     v2.x,v2.y,v2.z,v2.w, v3.x,v3.y};
                    ull wd[14];
                    #pragma unroll
                    for (int u = 0; u < 14; ++u) wd[u] = dup2(win[u]);
                    #pragma unroll
                    for (int dj = 0; dj < 7; ++dj) {
                        ull wp = pk2(wcur[dj], wprev[dj]);   // (row rr, row rr+1)
                        #pragma unroll
                        for (int j = 0; j < 8; ++j) fma2(acc[j], wp, wd[dj + j]);
                    }
                }
                #pragma unroll
                for (int u = 0; u < 7; ++u) wprev[u] = wcur[u];
            }
            float a0[8], a1[8];
            #pragma unroll
            for (int j = 0; j < 8; ++j) {
                float2 f = up2(acc[j]); a0[j] = f.x; a1[j] = f.y;
            }
            float* h0 = hd + dc_c*HD_P + dc_rr*8;
            *(float4*)(h0)      = make_float4(a0[0], a0[1], a0[2], a0[3]);
            *(float4*)(h0 + 4)  = make_float4(a0[4], a0[5], a0[6], a0[7]);
            *(float4*)(h0 + 8)  = make_float4(a1[0], a1[1], a1[2], a1[3]);
            *(float4*)(h0 + 12) = make_float4(a1[4], a1[5], a1[6], a1[7]);
        }
        {   // coalesced copy of pre-transposed weights into smem
            const float* s1 = g_wt1[e];
            #pragma unroll
            for (int i = 0; i < 8; ++i) {
                int idx = (t + i*256) * 4;
                *(float4*)(wt1 + idx) = *(const float4*)(s1 + idx);
            }
            const float* s2 = g_wt2[e];
            #pragma unroll
            for (int i = 0; i < 4; ++i) {
                int idx = (t + i*256) * 4;
                *(float4*)(wt2 + idx) = *(const float4*)(s2 + idx);
            }
        }
        __syncthreads();

        // ================= Phase B: LayerNorm over 64 positions =============
        {
            int c   = warp*8 + (lane >> 2);
            int sub = lane & 3;
            float* hc = hd + c*HD_P + sub*16;
            float v[16];
            #pragma unroll
            for (int u = 0; u < 4; ++u) {
                float4 f = *(const float4*)(hc + u*4);
                v[u*4+0]=f.x; v[u*4+1]=f.y; v[u*4+2]=f.z; v[u*4+3]=f.w;
            }
            float sum = 0.f, sq = 0.f;
            #pragma unroll
            for (int u = 0; u < 16; ++u) { sum += v[u]; sq += v[u]*v[u]; }
            sum += __shfl_xor_sync(0xFFFFFFFFu, sum, 1);
            sq  += __shfl_xor_sync(0xFFFFFFFFu, sq, 1);
            sum += __shfl_xor_sync(0xFFFFFFFFu, sum, 2);
            sq  += __shfl_xor_sync(0xFFFFFFFFu, sq, 2);
            float mu   = sum * (1.f/64.f);
            float var  = sq  * (1.f/64.f) - mu*mu;
            float rstd = rsqrtf(var + 1e-5f);
            const float* lw = ln_w + e*64 + sub*16;
            const float* lb = ln_b + e*64 + sub*16;
            #pragma unroll
            for (int u = 0; u < 16; ++u)
                v[u] = (v[u] - mu) * rstd * __ldg(&lw[u]) + __ldg(&lb[u]);
            #pragma unroll
            for (int u = 0; u < 4; ++u)
                *(float4*)(hc + u*4) = make_float4(v[u*4+0],v[u*4+1],v[u*4+2],v[u*4+3]);
        }
        __syncthreads();

        // ============== Phase C1: GEMM1 (pw_in a & g), f32x2 ================
        // acc packed over output pairs: rr=0 -> (ob,ob+1), rr=1 -> (ob+2,ob+3)
        ull aA[2][4], aG[2][4];
        #pragma unroll
        for (int rr = 0; rr < 2; ++rr)
            #pragma unroll
            for (int q = 0; q < 4; ++q) { aA[rr][q] = 0ull; aG[rr][q] = 0ull; }

        #pragma unroll 4
        for (int k = 0; k < 64; ++k) {
            float4 wa = *(const float4*)(wt1 + (k << 7) + ob);
            float4 wg = *(const float4*)(wt1 + (k << 7) + 64 + ob);
            float4 h  = *(const float4*)(hd  + k*HD_P + pb);
            ull waP0 = pk2(wa.x, wa.y), waP1 = pk2(wa.z, wa.w);
            ull wgP0 = pk2(wg.x, wg.y), wgP1 = pk2(wg.z, wg.w);
            ull h0 = dup2(h.x), h1 = dup2(h.y), h2 = dup2(h.z), h3 = dup2(h.w);
            fma2(aA[0][0], waP0, h0); fma2(aA[0][1], waP0, h1);
            fma2(aA[0][2], waP0, h2); fma2(aA[0][3], waP0, h3);
            fma2(aA[1][0], waP1, h0); fma2(aA[1][1], waP1, h1);
            fma2(aA[1][2], waP1, h2); fma2(aA[1][3], waP1, h3);
            fma2(aG[0][0], wgP0, h0); fma2(aG[0][1], wgP0, h1);
            fma2(aG[0][2], wgP0, h2); fma2(aG[0][3], wgP0, h3);
            fma2(aG[1][0], wgP1, h0); fma2(aG[1][1], wgP1, h1);
            fma2(aG[1][2], wgP1, h2); fma2(aG[1][3], wgP1, h3);
        }
        __syncthreads();   // all reads of hd done before GLU overwrites it

        // ============== Phase C2: GLU -> hd (reused) ========================
        {
            const float* bi = pwi_b + e*128;
            #pragma unroll
            for (int rr = 0; rr < 2; ++rr) {
                float sA0[4], sA1[4], sG0[4], sG1[4];
                #pragma unroll
                for (int q = 0; q < 4; ++q) {
                    float2 fa = up2(aA[rr][q]); sA0[q] = fa.x; sA1[q] = fa.y;
                    float2 fg = up2(aG[rr][q]); sG0[q] = fg.x; sG1[q] = fg.y;
                }
                int o0 = ob + 2*rr, o1 = o0 + 1;
                float ba0 = __ldg(&bi[o0]),     ba1 = __ldg(&bi[o1]);
                float bg0 = __ldg(&bi[64+o0]),  bg1 = __ldg(&bi[64+o1]);
                float r0[4], r1[4];
                #pragma unroll
                for (int q = 0; q < 4; ++q) {
                    float a = sA0[q] + ba0, g = sG0[q] + bg0;
                    r0[q] = a * (1.f / (1.f + __expf(-a))) * g;
                    float a2 = sA1[q] + ba1, g2 = sG1[q] + bg1;
                    r1[q] = a2 * (1.f / (1.f + __expf(-a2))) * g2;
                }
                *(float4*)(hd + o0*HD_P + pb) = make_float4(r0[0],r0[1],r0[2],r0[3]);
                *(float4*)(hd + o1*HD_P + pb) = make_float4(r1[0],r1[1],r1[2],r1[3]);
            }
        }
        __syncthreads();

        // ============== Phase D: GEMM2 (pw_out), f32x2 ======================
        {
            ull acc[2][4];
            #pragma unroll
            for (int rr = 0; rr < 2; ++rr)
                #pragma unroll
                for (int q = 0; q < 4; ++q) acc[rr][q] = 0ull;

            #pragma unroll 4
            for (int k = 0; k < 64; ++k) {
                float4 w = *(const float4*)(wt2 + (k << 6) + ob);
                float4 h = *(const float4*)(hd  + k*HD_P + pb);
                ull wP0 = pk2(w.x, w.y), wP1 = pk2(w.z, w.w);
                ull h0 = dup2(h.x), h1 = dup2(h.y), h2 = dup2(h.z), h3 = dup2(h.w);
                fma2(acc[0][0], wP0, h0); fma2(acc[0][1], wP0, h1);
                fma2(acc[0][2], wP0, h2); fma2(acc[0][3], wP0, h3);
                fma2(acc[1][0], wP1, h0); fma2(acc[1][1], wP1, h1);
                fma2(acc[1][2], wP1, h2); fma2(acc[1][3], wP1, h3);
            }
            const float* bo = pwo_b + e*64;
            #pragma unroll
            for (int rr = 0; rr < 2; ++rr) {
                int o0 = ob + 2*rr;
                float b0 = __ldg(&bo[o0]), b1 = __ldg(&bo[o0+1]);
                #pragma unroll
                for (int q = 0; q < 4; ++q) {
                    float2 f = up2(acc[rr][q]);
                    osum[2*rr][q]   += we * (f.x + b0);
                    osum[2*rr+1][q] += we * (f.y + b1);
                }
            }
        }
        __syncthreads();   // hd/wt free for next expert
    }

    // ---- out = x + sum_k w_k * h_k ----
    {
        const int ir = pb >> 3;
        const int j0 = pb & 7;
        #pragma unroll
        for (int r = 0; r < 4; ++r) {
            int o = ob + r;
            const float* xr = xs + o*XS_CP + ir*16 + 3 + j0;
            float4 v;
            v.x = xr[0] + osum[r][0];
            v.y = xr[1] + osum[r][1];
            v.z = xr[2] + osum[r][2];
            v.w = xr[3] + osum[r][3];
            *(float4*)(out + gbase + (long)o*131072 + ir*128 + j0) = v;
        }
    }
}

// ---------------------------------------------------------------------------
extern "C" void kernel_launch(void* const* d_in, const int* in_sizes, int n_in,
                              void* d_out, int out_size)
{
    const float* x        = (const float*)d_in[0];
    const float* router_w = (const float*)d_in[1];
    const float* router_b = (const float*)d_in[2];
    const float* dw_w     = (const float*)d_in[3];
    const float* dw_b     = (const float*)d_in[4];
    const float* ln_w     = (const float*)d_in[5];
    const float* ln_b     = (const float*)d_in[6];
    const float* pwi_w    = (const float*)d_in[7];
    const float* pwi_b    = (const float*)d_in[8];
    const float* pwo_w    = (const float*)d_in[9];
    const float* pwo_b    = (const float*)d_in[10];
    float* out = (float*)d_out;

    transpose_kernel<<<8, 256>>>(pwi_w, pwo_w);
    router_kernel<<<NPATCH, 256>>>(x, router_w, router_b);

    const int smem_bytes = SMEM_FLOATS * sizeof(float);   // 100352
    cudaFuncSetAttribute(moe_kernel,
                         cudaFuncAttributeMaxDynamicSharedMemorySize, smem_bytes);
    moe_kernel<<<4096, 256, smem_bytes>>>(x, dw_w, dw_b, ln_w, ln_b,
                                          pwi_b, pwo_b, out);
}

// round 9
// speedup vs baseline: 3.1575x; 1.3254x over previous
#include <cuda_runtime.h>
#include <cstdint>
#include <cmath>

// ---------------------------------------------------------------------------
// SpatialPatchMoE round 9 = round 7 re-bench attempt #3 (broker failures in
// rounds 7 & 8; identical signature previously resolved as infra in round 2).
// Legacy mma.sync tf32 tensor-core GEMMs (sm_100-safe).
// Block = (patch, l) slice. Per expert:
//   dwconv(f32x2) -> H[64 pos][64 ch]  (tf32 after LN)
//   GEMM1 (mma.sync m16n8k8): D1[64 x 128] = H x W1interleaved -> GLU in regs
//        -> XG[64 pos][64]
//   GEMM2: D2[64 x 64] = XG x W2 -> osum regs (weighted)
// out = x + sum_e we*(D2_e + b)
// ---------------------------------------------------------------------------

#define NPATCH 512
typedef unsigned long long ull;

// smem layout (floats)
#define XS_CP   132                  // xs pitch: 8 rows x 16 + 4
#define H_OFF   8704                 // H pitch 68  -> 4352
#define H_P     68
#define W2_OFF  13056                // W2 pitch 72 -> 4608
#define W2_P    72
#define XG_OFF  17664                // XG pitch 68 -> 4352
#define XG_P    68
#define W1_P    136                  // W1 lives in BUF0 (offset 0), 64*136=8704
#define SMEM_FLOATS 22016            // 88064 bytes

__device__ int   g_topi[NPATCH][2];
__device__ float g_topw[NPATCH][2];
__device__ __align__(16) float g_w1f[8][64*W1_P];  // [e][c][n'=2o|2o+1] tf32
__device__ __align__(16) float g_w2f[8][64*W2_P];  // [e][c][o] tf32

// ---- f32x2 helpers (dwconv) ----
__device__ __forceinline__ ull pk2(float lo, float hi) {
    ull r; asm("mov.b64 %0, {%1, %2};" : "=l"(r) : "f"(lo), "f"(hi)); return r;
}
__device__ __forceinline__ ull dup2(float v) {
    ull r; asm("mov.b64 %0, {%1, %1};" : "=l"(r) : "f"(v)); return r;
}
__device__ __forceinline__ void fma2(ull& d, ull a, ull b) {
    asm("fma.rn.f32x2 %0, %1, %2, %0;" : "+l"(d) : "l"(a), "l"(b));
}
__device__ __forceinline__ float2 up2(ull v) {
    float2 f; asm("mov.b64 {%0, %1}, %2;" : "=f"(f.x), "=f"(f.y) : "l"(v)); return f;
}
// tf32 round-to-nearest: destination is a .b32 register
__device__ __forceinline__ float to_tf32(float x) {
    uint32_t r; asm("cvt.rna.tf32.f32 %0, %1;" : "=r"(r) : "f"(x));
    return __uint_as_float(r);
}

// tf32 warp MMA: D[16x8] += A[16x8] * B[8x8]
__device__ __forceinline__ void mma8(float* d, uint32_t a0, uint32_t a1,
                                     uint32_t a2, uint32_t a3,
                                     uint32_t b0, uint32_t b1) {
    asm volatile(
        "mma.sync.aligned.m16n8k8.row.col.f32.tf32.tf32.f32 "
        "{%0,%1,%2,%3}, {%4,%5,%6,%7}, {%8,%9}, {%0,%1,%2,%3};"
        : "+f"(d[0]), "+f"(d[1]), "+f"(d[2]), "+f"(d[3])
        : "r"(a0), "r"(a1), "r"(a2), "r"(a3), "r"(b0), "r"(b1));
}
__device__ __forceinline__ uint32_t fu(float x) { return __float_as_uint(x); }

// ---------------------------------------------------------------------------
// Pre-pass: tf32-round weights; W1 a/g-interleaved + transposed, W2 transposed
// ---------------------------------------------------------------------------
__global__ __launch_bounds__(256) void prepass_kernel(
    const float* __restrict__ pwi_w, const float* __restrict__ pwo_w)
{
    int e = blockIdx.x, t = threadIdx.x;
    const float* s1 = pwi_w + (long)e*8192;
    float* d1 = g_w1f[e];
    for (int i = t; i < 8192; i += 256) {
        int o = i >> 6, c = i & 63;
        int np = (o < 64) ? (2*o) : (2*(o-64) + 1);
        d1[c*W1_P + np] = to_tf32(s1[i]);
    }
    const float* s2 = pwo_w + (long)e*4096;
    float* d2 = g_w2f[e];
    for (int i = t; i < 4096; i += 256) {
        int o = i >> 6, c = i & 63;
        d2[c*W2_P + o] = to_tf32(s2[i]);
    }
}

// ---------------------------------------------------------------------------
// Router (unchanged, proven)
// ---------------------------------------------------------------------------
__global__ __launch_bounds__(256) void router_kernel(
    const float* __restrict__ x,
    const float* __restrict__ rw,
    const float* __restrict__ rb)
{
    int n  = blockIdx.x;
    int b  = n >> 8;
    int ph = (n >> 4) & 15;
    int pw = n & 15;
    int t = threadIdx.x, lane = t & 31, warp = t >> 5;
    int i4 = lane >> 3, j = lane & 7;

    __shared__ float sm[64];
    __shared__ float logits[8];

    for (int r = 0; r < 8; ++r) {
        int c = warp * 8 + r;
        const float* xc = x + ((long)b*64 + c)*131072 + (ph*8)*128 + pw*8;
        float s = 0.f;
        #pragma unroll
        for (int l = 0; l < 8; ++l) {
            long base = (long)l * 16384;
            s += xc[base + i4*128 + j];
            s += xc[base + (i4+4)*128 + j];
        }
        #pragma unroll
        for (int off = 16; off; off >>= 1) s += __shfl_xor_sync(0xFFFFFFFFu, s, off);
        if (lane == 0) sm[c] = s * (1.f/512.f);
    }
    __syncthreads();
    if (t < 8) {
        float acc = rb[t];
        const float* w = rw + t*64;
        #pragma unroll
        for (int c = 0; c < 64; ++c) acc += sm[c] * w[c];
        logits[t] = acc;
    }
    __syncthreads();
    if (t == 0) {
        int i0 = 0; float v0 = logits[0];
        #pragma unroll
        for (int e = 1; e < 8; ++e) if (logits[e] > v0) { v0 = logits[e]; i0 = e; }
        int i1 = -1; float v1 = -3.4e38f;
        #pragma unroll
        for (int e = 0; e < 8; ++e) if (e != i0 && logits[e] > v1) { v1 = logits[e]; i1 = e; }
        float e1  = __expf(v1 - v0);
        float inv = 1.f / (1.f + e1);
        g_topi[n][0] = i0; g_topi[n][1] = i1;
        g_topw[n][0] = inv; g_topw[n][1] = e1 * inv;
    }
}

// ---------------------------------------------------------------------------
// Main kernel: grid 4096 = (patch, l); 256 threads = 8 warps.
// ---------------------------------------------------------------------------
extern __shared__ float smem_dyn[];

__global__ __launch_bounds__(256, 2) void moe_kernel(
    const float* __restrict__ x,
    const float* __restrict__ dw_w,  const float* __restrict__ dw_b,
    const float* __restrict__ ln_w,  const float* __restrict__ ln_b,
    const float* __restrict__ pwi_b, const float* __restrict__ pwo_b,
    float* __restrict__ out)
{
    float* buf0 = smem_dyn;             // xs (dwconv input) then W1
    float* H    = smem_dyn + H_OFF;     // [pos][ch] pitch 68
    float* W2s  = smem_dyn + W2_OFF;    // [k][o]   pitch 72
    float* XG   = smem_dyn + XG_OFF;    // [pos][o] pitch 68

    int s = blockIdx.x;
    int n = s >> 3, l = s & 7;
    int b = n >> 8, ph = (n >> 4) & 15, pwn = n & 15;
    int t = threadIdx.x, lane = t & 31, wid = t >> 5;

    const long gbase = (long)b*64*131072 + (long)l*16384 + (ph*8)*128 + pwn*8;

    int   e0 = g_topi[n][0], e1i = g_topi[n][1];
    float wgt0 = g_topw[n][0], wgt1 = g_topw[n][1];

    // warp MMA tiling
    const int gid = lane >> 2;              // 0..7
    const int tig = lane & 3;               // 0..3
    const int mt  = wid & 3;                // m-tile (16 positions)
    const int nh  = wid >> 2;               // n-half (0..1)
    const int r0  = mt*16 + gid, r1 = r0 + 8;

    // dwconv per-thread assignment
    const int dc_c  = t >> 2;               // channel 0..63
    const int dc_rr = (t & 3) * 2;          // output rows rr, rr+1

    float osum[4][4];
    #pragma unroll
    for (int jt = 0; jt < 4; ++jt)
        #pragma unroll
        for (int q = 0; q < 4; ++q) osum[jt][q] = 0.f;

    for (int kk = 0; kk < 2; ++kk) {
        const int   e  = kk ? e1i : e0;
        const float we = kk ? wgt1 : wgt0;

        // ---- load xs (padded) into buf0 + copy W2(e) ----------------------
        for (int rid = t; rid < 512; rid += 256) {
            float* row = buf0 + (rid >> 3)*XS_CP + (rid & 7)*16;
            row[0] = 0.f; row[1] = 0.f; row[2] = 0.f;
            row[11] = 0.f; row[12] = 0.f; row[13] = 0.f;
        }
        for (int idx = t; idx < 4096; idx += 256) {
            int c = idx >> 6, p = idx & 63, i = p >> 3, j = p & 7;
            buf0[c*XS_CP + i*16 + 3 + j] = x[gbase + (long)c*131072 + i*128 + j];
        }
        {
            const float4* s2 = (const float4*)g_w2f[e];
            float4* d2 = (float4*)W2s;
            for (int i = t; i < 64*W2_P/4; i += 256) d2[i] = s2[i];
        }
        __syncthreads();

        // ---- dwconv 7x7 (f32x2 over row pair) -> H[pos][ch] ---------------
        {
            const float* W = dw_w + ((long)e*64 + dc_c)*49;
            float bias = __ldg(&dw_b[e*64 + dc_c]);
            ull acc[8];
            #pragma unroll
            for (int j = 0; j < 8; ++j) acc[j] = dup2(bias);

            float wprev[7];
            #pragma unroll
            for (int u = 0; u < 7; ++u) wprev[u] = 0.f;

            #pragma unroll
            for (int di = 0; di < 8; ++di) {
                float wcur[7];
                #pragma unroll
                for (int u = 0; u < 7; ++u)
                    wcur[u] = (di <= 6) ? __ldg(&W[di*7 + u]) : 0.f;
                int ii = dc_rr + di - 3;
                if (ii >= 0 && ii <= 7) {
                    const float* xr = buf0 + dc_c*XS_CP + ii*16;
                    float4 v0 = *(const float4*)(xr);
                    float4 v1 = *(const float4*)(xr + 4);
                    float4 v2 = *(const float4*)(xr + 8);
                    float4 v3 = *(const float4*)(xr + 12);
                    float win[14] = {v0.x,v0.y,v0.z,v0.w, v1.x,v1.y,v1.z,v1.w,
                                     v2.x,v2.y,v2.z,v2.w, v3.x,v3.y};
                    ull wd[14];
                    #pragma unroll
                    for (int u = 0; u < 14; ++u) wd[u] = dup2(win[u]);
                    #pragma unroll
                    for (int dj = 0; dj < 7; ++dj) {
                        ull wp = pk2(wcur[dj], wprev[dj]);
                        #pragma unroll
                        for (int j = 0; j < 8; ++j) fma2(acc[j], wp, wd[dj + j]);
                    }
                }
                #pragma unroll
                for (int u = 0; u < 7; ++u) wprev[u] = wcur[u];
            }
            #pragma unroll
            for (int j = 0; j < 8; ++j) {
                float2 f = up2(acc[j]);
                int p0 = dc_rr*8 + j;            // row dc_rr
                H[p0*H_P + dc_c]       = f.x;
                H[(p0 + 8)*H_P + dc_c] = f.y;    // row dc_rr+1
            }
        }
        __syncthreads();

        // ---- LayerNorm over 64 pos per channel (staggered, tf32 out) ------
        // + copy W1(e) into buf0 (xs no longer needed)
        {
            const float4* s1 = (const float4*)g_w1f[e];
            float4* d1 = (float4*)buf0;
            for (int i = t; i < 64*W1_P/4; i += 256) d1[i] = s1[i];

            int ch = t >> 2, q = t & 3;
            float v[16];
            float sum = 0.f, sq = 0.f;
            #pragma unroll
            for (int u = 0; u < 16; ++u) {
                int pos = q*16 + ((u + 2*q) & 15);
                float vv = H[pos*H_P + ch];
                v[u] = vv; sum += vv; sq += vv*vv;
            }
            sum += __shfl_xor_sync(0xFFFFFFFFu, sum, 1);
            sq  += __shfl_xor_sync(0xFFFFFFFFu, sq, 1);
            sum += __shfl_xor_sync(0xFFFFFFFFu, sum, 2);
            sq  += __shfl_xor_sync(0xFFFFFFFFu, sq, 2);
            float mu   = sum * (1.f/64.f);
            float var  = sq  * (1.f/64.f) - mu*mu;
            float rstd = rsqrtf(var + 1e-5f);
            #pragma unroll
            for (int u = 0; u < 16; ++u) {
                int pos = q*16 + ((u + 2*q) & 15);
                float vv = (v[u] - mu) * rstd * __ldg(&ln_w[e*64 + pos])
                           + __ldg(&ln_b[e*64 + pos]);
                H[pos*H_P + ch] = to_tf32(vv);
            }
        }
        __syncthreads();

        // ---- GEMM1: D1[64 x 128(int)] = H x W1, GLU in regs -> XG ---------
        {
            float ac[8][4];
            #pragma unroll
            for (int jt = 0; jt < 8; ++jt)
                #pragma unroll
                for (int q = 0; q < 4; ++q) ac[jt][q] = 0.f;

            #pragma unroll
            for (int ks = 0; ks < 8; ++ks) {
                int k0 = ks*8 + tig, k1 = k0 + 4;
                uint32_t a0 = fu(H[r0*H_P + k0]);
                uint32_t a1 = fu(H[r1*H_P + k0]);
                uint32_t a2 = fu(H[r0*H_P + k1]);
                uint32_t a3 = fu(H[r1*H_P + k1]);
                #pragma unroll
                for (int jt = 0; jt < 8; ++jt) {
                    int nb = nh*64 + jt*8 + gid;
                    uint32_t b0 = fu(buf0[k0*W1_P + nb]);
                    uint32_t b1 = fu(buf0[k1*W1_P + nb]);
                    mma8(ac[jt], a0, a1, a2, a3, b0, b1);
                }
            }
            // GLU: interleaved layout -> (c0,c1)=(a,g) @ row r0; (c2,c3) @ r1
            const float* bi = pwi_b + e*128;
            #pragma unroll
            for (int jt = 0; jt < 8; ++jt) {
                int o = nh*32 + jt*4 + tig;
                float ba = __ldg(&bi[o]), bg = __ldg(&bi[64 + o]);
                float a = ac[jt][0] + ba, g = ac[jt][1] + bg;
                XG[r0*XG_P + o] = to_tf32(a * (1.f/(1.f + __expf(-a))) * g);
                a = ac[jt][2] + ba; g = ac[jt][3] + bg;
                XG[r1*XG_P + o] = to_tf32(a * (1.f/(1.f + __expf(-a))) * g);
            }
        }
        __syncthreads();

        // ---- GEMM2: D2[64 x 64] = XG x W2 -> osum (weighted) --------------
        {
            float ac[4][4];
            #pragma unroll
            for (int jt = 0; jt < 4; ++jt)
                #pragma unroll
                for (int q = 0; q < 4; ++q) ac[jt][q] = 0.f;

            #pragma unroll
            for (int ks = 0; ks < 8; ++ks) {
                int k0 = ks*8 + tig, k1 = k0 + 4;
                uint32_t a0 = fu(XG[r0*XG_P + k0]);
                uint32_t a1 = fu(XG[r1*XG_P + k0]);
                uint32_t a2 = fu(XG[r0*XG_P + k1]);
                uint32_t a3 = fu(XG[r1*XG_P + k1]);
                #pragma unroll
                for (int jt = 0; jt < 4; ++jt) {
                    int nb = nh*32 + jt*8 + gid;
                    uint32_t b0 = fu(W2s[k0*W2_P + nb]);
                    uint32_t b1 = fu(W2s[k1*W2_P + nb]);
                    mma8(ac[jt], a0, a1, a2, a3, b0, b1);
                }
            }
            const float* bo = pwo_b + e*64;
            #pragma unroll
            for (int jt = 0; jt < 4; ++jt) {
                int c0 = nh*32 + jt*8 + tig*2;
                float b0 = __ldg(&bo[c0]), b1 = __ldg(&bo[c0+1]);
                osum[jt][0] += we * (ac[jt][0] + b0);
                osum[jt][1] += we * (ac[jt][1] + b1);
                osum[jt][2] += we * (ac[jt][2] + b0);
                osum[jt][3] += we * (ac[jt][3] + b1);
            }
        }
        __syncthreads();   // buffers free for next expert
    }

    // ---- out = x + sum_e we*h_e  (D-fragment mapping) ----
    {
        int i0 = r0 >> 3, j0 = r0 & 7;     // pos r0
        int i1 = r1 >> 3, j1 = r1 & 7;     // pos r1
        #pragma unroll
        for (int jt = 0; jt < 4; ++jt) {
            int c0 = nh*32 + jt*8 + tig*2;
            long idx00 = gbase + (long)c0*131072     + i0*128 + j0;
            long idx01 = gbase + (long)(c0+1)*131072 + i0*128 + j0;
            long idx10 = gbase + (long)c0*131072     + i1*128 + j1;
            long idx11 = gbase + (long)(c0+1)*131072 + i1*128 + j1;
            out[idx00] = __ldg(&x[idx00]) + osum[jt][0];
            out[idx01] = __ldg(&x[idx01]) + osum[jt][1];
            out[idx10] = __ldg(&x[idx10]) + osum[jt][2];
            out[idx11] = __ldg(&x[idx11]) + osum[jt][3];
        }
    }
}

// ---------------------------------------------------------------------------
extern "C" void kernel_launch(void* const* d_in, const int* in_sizes, int n_in,
                              void* d_out, int out_size)
{
    const float* x        = (const float*)d_in[0];
    const float* router_w = (const float*)d_in[1];
    const float* router_b = (const float*)d_in[2];
    const float* dw_w     = (const float*)d_in[3];
    const float* dw_b     = (const float*)d_in[4];
    const float* ln_w     = (const float*)d_in[5];
    const float* ln_b     = (const float*)d_in[6];
    const float* pwi_w    = (const float*)d_in[7];
    const float* pwi_b    = (const float*)d_in[8];
    const float* pwo_w    = (const float*)d_in[9];
    const float* pwo_b    = (const float*)d_in[10];
    float* out = (float*)d_out;

    prepass_kernel<<<8, 256>>>(pwi_w, pwo_w);
    router_kernel<<<NPATCH, 256>>>(x, router_w, router_b);

    const int smem_bytes = SMEM_FLOATS * sizeof(float);   // 88064
    cudaFuncSetAttribute(moe_kernel,
                         cudaFuncAttributeMaxDynamicSharedMemorySize, smem_bytes);
    moe_kernel<<<4096, 256, smem_bytes>>>(x, dw_w, dw_b, ln_w, ln_b,
                                          pwi_b, pwo_b, out);
}